// round 15
// baseline (speedup 1.0000x reference)
#include <cuda_runtime.h>
#include <cuda_fp16.h>
#include <math.h>
#include <stdint.h>

#define B_ 4
#define T_ 1024
#define E_ 256
#define V_ 32000
#define NTOK (B_*T_)
#define K1_ 576
#define H_  512
#define SCH 64                 // scan chunk length
#define NCH (T_/SCH)           // 16 chunks

// ------------------------- device scratch (static; no allocs) --------------
__device__ float  g_c[NTOK * 24];
__device__ float  g_tail[B_ * NCH * K1_];    // per-chunk tail partials
__device__ __half g_sH[NTOK * K1_];          // fp16 states
__device__ __half g_w1H[H_ * K1_];
__device__ __half g_hH[NTOK * H_];           // fp16 gelu hidden
__device__ __half g_w2H[(size_t)V_ * H_];

__device__ __forceinline__ float warp_sum(float v) {
#pragma unroll
    for (int o = 16; o > 0; o >>= 1) v += __shfl_xor_sync(0xffffffffu, v, o);
    return v;
}
__device__ __forceinline__ uint32_t smem_u32(const void* p) {
    uint32_t a;
    asm("{ .reg .u64 t; cvta.to.shared.u64 t, %1; cvt.u32.u64 %0, t; }" : "=r"(a) : "l"(p));
    return a;
}

// ---------------------------------------------------------------------------
// Kernel A: token features + W1 convert (critical path for scan/GEMM1)
// ---------------------------------------------------------------------------
#define PRE_THREADS 384
#define W1_F4 ((H_ * K1_) / 4)
#define W1_BLK ((W1_F4 + PRE_THREADS - 1) / PRE_THREADS)

__global__ void __launch_bounds__(PRE_THREADS)
token_w1_kernel(const int* __restrict__ ids, const float* __restrict__ emb,
                const float* __restrict__ Wax, const float* __restrict__ bax,
                const float* __restrict__ gax, const float* __restrict__ betax,
                const float* __restrict__ Wc,  const float* __restrict__ bc,
                const float* __restrict__ gc,  const float* __restrict__ betac,
                const float* __restrict__ W1)
{
    const int bid = blockIdx.x;
    const int tid = threadIdx.x;

    if (bid >= NTOK) {
        int idx = (bid - NTOK) * PRE_THREADS + tid;
        if (idx < W1_F4) {
            float4 v = ((const float4*)W1)[idx];
            __half2 a = __floats2half2_rn(v.x, v.y);
            __half2 b = __floats2half2_rn(v.z, v.w);
            ((__half2*)g_w1H)[idx * 2 + 0] = a;
            ((__half2*)g_w1H)[idx * 2 + 1] = b;
        }
        return;
    }

    __shared__ float xsh[E_];
    __shared__ float ash[12];
    const int n = bid;
    const int id = ids[n];
    for (int e = tid; e < E_; e += PRE_THREADS) xsh[e] = emb[(size_t)id * E_ + e];
    __syncthreads();
    const int w = tid >> 5, lane = tid & 31;
    {
        const float* wr = Wax + w * E_;
        float p = 0.f;
#pragma unroll
        for (int e = lane; e < E_; e += 32) p += xsh[e] * wr[e];
        p = warp_sum(p);
        if (lane == 0) ash[w] = p + bax[w];
    }
    __syncthreads();
    if (w == 0) {
        float v = (lane < 12) ? ash[lane] : 0.f;
        float mu = warp_sum(v) * (1.f / 12.f);
        float dv = (lane < 12) ? (v - mu) : 0.f;
        float var = warp_sum(dv * dv) * (1.f / 12.f);
        float r = rsqrtf(var + 1e-5f);
        if (lane < 12) ash[lane] = tanhf(dv * r * gax[lane] + betax[lane]);
        __syncwarp();
        float cr = 0.f;
        if (lane < 24) {
            cr = bc[lane];
#pragma unroll
            for (int k = 0; k < 12; k++) cr += ash[k] * Wc[lane * 12 + k];
        }
        float v2 = (lane < 24) ? cr : 0.f;
        float mu2 = warp_sum(v2) * (1.f / 24.f);
        float dv2 = (lane < 24) ? (cr - mu2) : 0.f;
        float var2 = warp_sum(dv2 * dv2) * (1.f / 24.f);
        float r2 = rsqrtf(var2 + 1e-5f);
        if (lane < 24) g_c[n * 24 + lane] = tanhf(dv2 * r2 * gc[lane] + betac[lane]);
    }
}

// ---------------------------------------------------------------------------
// Kernel W (side stream): W2 fp32->fp16
// ---------------------------------------------------------------------------
#define W2_F4 ((int)(((size_t)V_ * H_) / 4))
#define W2C_THREADS 256
#define W2C_HALF (W2_F4 / 2)
#define W2C_GRID (W2C_HALF / W2C_THREADS)

__global__ void __launch_bounds__(W2C_THREADS)
w2conv_kernel(const float* __restrict__ W2)
{
    int idx = blockIdx.x * W2C_THREADS + threadIdx.x;
#pragma unroll
    for (int h = 0; h < 2; h++) {
        int i = idx + h * W2C_HALF;
        float4 v = ((const float4*)W2)[i];
        __half2 a = __floats2half2_rn(v.x, v.y);
        __half2 b = __floats2half2_rn(v.z, v.w);
        ((__half2*)g_w2H)[i * 2 + 0] = a;
        ((__half2*)g_w2H)[i * 2 + 1] = b;
    }
}

// ---------------------------------------------------------------------------
// Parallel scan, 2 phases, NO fp32 state round-trip.
// S1: per (chunk k, batch b), run the 64-step recurrence in registers and
//     write ONLY the tail partial.
// ---------------------------------------------------------------------------
__global__ void __launch_bounds__(576)
scan_tail_kernel(const float* __restrict__ decay_p, const float* __restrict__ mix_p)
{
    __shared__ float csh[SCH * 24];
    const int k = blockIdx.x, b = blockIdx.y, tid = threadIdx.x;
    const int i = tid / 24, j = tid % 24;
    const int t0 = k * SCH;
    const float d = 1.f / (1.f + expf(-decay_p[0]));
    const float m = 1.f / (1.f + expf(-mix_p[0]));

    for (int idx = tid; idx < SCH * 24; idx += 576)
        csh[idx] = g_c[(b * T_ + t0) * 24 + idx];
    __syncthreads();

    float p = 0.f;
#pragma unroll 8
    for (int tt = 0; tt < SCH; tt++)
        p = d * p + m * csh[tt * 24 + i] * csh[tt * 24 + j];
    g_tail[(b * NCH + k) * K1_ + tid] = p;
}

// S2: load ALL needed tails upfront (independent loads -> MLP overlap, and
// they overlap the csh smem fill), Horner in the SAME ascending-j order,
// then rerun the chunk recurrence seeded with the carry and emit fp16.
__global__ void __launch_bounds__(576)
scan_emit_kernel(const float* __restrict__ decay_p, const float* __restrict__ mix_p,
                 float* __restrict__ final_out)
{
    __shared__ float csh[SCH * 24];
    const int k = blockIdx.x, b = blockIdx.y, tid = threadIdx.x;
    const int i = tid / 24, j = tid % 24;
    const int t0 = k * SCH;
    const float d = 1.f / (1.f + expf(-decay_p[0]));
    const float m = 1.f / (1.f + expf(-mix_p[0]));

    // batch all tail loads (≤ NCH-1 independent loads, in flight together)
    float P[NCH - 1];
#pragma unroll
    for (int jj = 0; jj < NCH - 1; jj++)
        P[jj] = (jj < k) ? g_tail[(b * NCH + jj) * K1_ + tid] : 0.f;

    // overlap: stage csh while the tail loads are still in flight
    for (int idx = tid; idx < SCH * 24; idx += 576)
        csh[idx] = g_c[(b * T_ + t0) * 24 + idx];

    float d64 = 1.f;
#pragma unroll
    for (int q = 0; q < SCH; q++) d64 *= d;

    float C = 0.f;
#pragma unroll
    for (int jj = 0; jj < NCH - 1; jj++)
        if (jj < k) C = d64 * C + P[jj];

    __syncthreads();

    float s = C;
#pragma unroll 8
    for (int tt = 0; tt < SCH; tt++) {
        s = d * s + m * csh[tt * 24 + i] * csh[tt * 24 + j];
        g_sH[(size_t)(b * T_ + t0 + tt) * K1_ + tid] = __float2half_rn(s);
    }
    if (k == NCH - 1) final_out[b * K1_ + tid] = s;
}

// ---------------------------------------------------------------------------
// mma.sync fp16 GEMM-NT (R8 config, untouched): BM=128, BN=128, BK=32.
// 128 threads = 4 warps (2m x 2n), warp tile 64x64. 3-stage cp.async, 2 CTA/SM.
// ---------------------------------------------------------------------------
#define PAD_K 40
#define TILE_H (128 * PAD_K)
#define STAGE_H (2 * TILE_H)
#define NSTAGE 3
#define GEMM_SMEM_BYTES (NSTAGE * STAGE_H * 2)   // 61440 B

template <bool GELU>
__global__ void __launch_bounds__(128, 2)
gemm_mma(const __half* __restrict__ A, const __half* __restrict__ Bm,
         const float* __restrict__ bias, float* __restrict__ outF,
         __half* __restrict__ outH, int N, int K)
{
    extern __shared__ __half sm[];
    const int tid  = threadIdx.x;
    const int wid  = tid >> 5, lane = tid & 31;
    const int wm   = wid >> 1;
    const int wn   = wid & 1;
    const int r0   = blockIdx.y * 128;
    const int c0   = blockIdx.x * 128;

    const uint32_t smb = smem_u32(sm);

    float acc[4][8][4];
#pragma unroll
    for (int i = 0; i < 4; i++)
#pragma unroll
        for (int j = 0; j < 8; j++)
#pragma unroll
            for (int q = 0; q < 4; q++) acc[i][j][q] = 0.f;

    const int NS = K / 32;

    auto load_stage = [&](int ci, int st) {
        const int k0 = ci * 32;
        const uint32_t aBase = smb + (uint32_t)(st * STAGE_H) * 2;
        const uint32_t bBase = aBase + (uint32_t)TILE_H * 2;
#pragma unroll
        for (int p = 0; p < 4; p++) {
            int idx = tid + p * 128;
            int row = idx >> 2;
            int c4  = idx & 3;
            const __half* gs = A + (size_t)(r0 + row) * K + k0 + c4 * 8;
            uint32_t sd = aBase + (uint32_t)(row * PAD_K + c4 * 8) * 2;
            asm volatile("cp.async.cg.shared.global [%0], [%1], 16;" :: "r"(sd), "l"(gs));
        }
#pragma unroll
        for (int p = 0; p < 4; p++) {
            int idx = tid + p * 128;
            int row = idx >> 2;
            int c4  = idx & 3;
            const __half* gs = Bm + (size_t)(c0 + row) * K + k0 + c4 * 8;
            uint32_t sd = bBase + (uint32_t)(row * PAD_K + c4 * 8) * 2;
            asm volatile("cp.async.cg.shared.global [%0], [%1], 16;" :: "r"(sd), "l"(gs));
        }
        asm volatile("cp.async.commit_group;" ::: "memory");
    };

    load_stage(0, 0);
    load_stage(1, 1);

    for (int ci = 0; ci < NS; ci++) {
        const int st = ci % NSTAGE;
        if (ci == NS - 1) asm volatile("cp.async.wait_group 0;" ::: "memory");
        else              asm volatile("cp.async.wait_group 1;" ::: "memory");
        __syncthreads();
        if (ci + 2 < NS) load_stage(ci + 2, (ci + 2) % NSTAGE);

        const uint32_t aBase = smb + (uint32_t)(st * STAGE_H) * 2;
        const uint32_t bBase = aBase + (uint32_t)TILE_H * 2;

#pragma unroll
        for (int kk = 0; kk < 2; kk++) {
            const int kb = kk * 16;
            uint32_t afr[4][4];
            uint32_t bfr[8][2];
#pragma unroll
            for (int mt = 0; mt < 4; mt++) {
                uint32_t addr = aBase +
                    (uint32_t)((wm * 64 + mt * 16 + (lane & 15)) * PAD_K + kb + (lane >> 4) * 8) * 2;
                asm volatile("ldmatrix.sync.aligned.m8n8.x4.shared.b16 {%0,%1,%2,%3}, [%4];"
                             : "=r"(afr[mt][0]), "=r"(afr[mt][1]), "=r"(afr[mt][2]), "=r"(afr[mt][3])
                             : "r"(addr));
            }
#pragma unroll
            for (int ntp = 0; ntp < 4; ntp++) {
                uint32_t row = wn * 64 + ntp * 16 + ((lane >> 4) & 1) * 8 + (lane & 7);
                uint32_t kof = kb + ((lane >> 3) & 1) * 8;
                uint32_t addr = bBase + (uint32_t)(row * PAD_K + kof) * 2;
                asm volatile("ldmatrix.sync.aligned.m8n8.x4.shared.b16 {%0,%1,%2,%3}, [%4];"
                             : "=r"(bfr[ntp * 2][0]),     "=r"(bfr[ntp * 2][1]),
                               "=r"(bfr[ntp * 2 + 1][0]), "=r"(bfr[ntp * 2 + 1][1])
                             : "r"(addr));
            }
#pragma unroll
            for (int mt = 0; mt < 4; mt++)
#pragma unroll
                for (int nt = 0; nt < 8; nt++) {
                    asm volatile(
                        "mma.sync.aligned.m16n8k16.row.col.f32.f16.f16.f32 "
                        "{%0,%1,%2,%3}, {%4,%5,%6,%7}, {%8,%9}, {%0,%1,%2,%3};"
                        : "+f"(acc[mt][nt][0]), "+f"(acc[mt][nt][1]),
                          "+f"(acc[mt][nt][2]), "+f"(acc[mt][nt][3])
                        : "r"(afr[mt][0]), "r"(afr[mt][1]), "r"(afr[mt][2]), "r"(afr[mt][3]),
                          "r"(bfr[nt][0]), "r"(bfr[nt][1]));
                }
        }
    }

    const int g  = lane >> 2;
    const int tg = lane & 3;
#pragma unroll
    for (int nt = 0; nt < 8; nt++) {
        const int col = c0 + wn * 64 + nt * 8 + tg * 2;
        const float bi0 = __ldg(bias + col);
        const float bi1 = __ldg(bias + col + 1);
#pragma unroll
        for (int mt = 0; mt < 4; mt++) {
            const int row = r0 + wm * 64 + mt * 16 + g;
            float x0 = acc[mt][nt][0] + bi0;
            float x1 = acc[mt][nt][1] + bi1;
            float x2 = acc[mt][nt][2] + bi0;
            float x3 = acc[mt][nt][3] + bi1;
            if (GELU) {
                x0 = 0.5f * x0 * (1.f + erff(x0 * 0.70710678118654752f));
                x1 = 0.5f * x1 * (1.f + erff(x1 * 0.70710678118654752f));
                x2 = 0.5f * x2 * (1.f + erff(x2 * 0.70710678118654752f));
                x3 = 0.5f * x3 * (1.f + erff(x3 * 0.70710678118654752f));
                *(__half2*)(outH + (size_t)row * N + col)       = __floats2half2_rn(x0, x1);
                *(__half2*)(outH + (size_t)(row + 8) * N + col) = __floats2half2_rn(x2, x3);
            } else {
                *(float2*)(outF + (size_t)row * N + col)       = make_float2(x0, x1);
                *(float2*)(outF + (size_t)(row + 8) * N + col) = make_float2(x2, x3);
            }
        }
    }
}

// ---------------------------------------------------------------------------
extern "C" void kernel_launch(void* const* d_in, const int* in_sizes, int n_in,
                              void* d_out, int out_size)
{
    const int*   ids    = (const int*)  d_in[0];
    const float* emb    = (const float*)d_in[1];
    const float* Wax    = (const float*)d_in[2];
    const float* bax    = (const float*)d_in[3];
    const float* gax    = (const float*)d_in[4];
    const float* betax  = (const float*)d_in[5];
    const float* Wc     = (const float*)d_in[6];
    const float* bc     = (const float*)d_in[7];
    const float* gc     = (const float*)d_in[8];
    const float* betac  = (const float*)d_in[9];
    const float* decayp = (const float*)d_in[10];
    const float* mixp   = (const float*)d_in[11];
    const float* W1     = (const float*)d_in[12];
    const float* b1     = (const float*)d_in[13];
    const float* W2     = (const float*)d_in[14];
    const float* b2     = (const float*)d_in[15];

    float* out       = (float*)d_out;
    float* logits    = out;
    float* final_out = out + (size_t)NTOK * V_;

    __half *sH, *w1H, *hH, *w2H;
    cudaGetSymbolAddress((void**)&sH,  g_sH);
    cudaGetSymbolAddress((void**)&w1H, g_w1H);
    cudaGetSymbolAddress((void**)&hH,  g_hH);
    cudaGetSymbolAddress((void**)&w2H, g_w2H);

    cudaFuncSetAttribute(gemm_mma<true>,  cudaFuncAttributeMaxDynamicSharedMemorySize, GEMM_SMEM_BYTES);
    cudaFuncSetAttribute(gemm_mma<false>, cudaFuncAttributeMaxDynamicSharedMemorySize, GEMM_SMEM_BYTES);

    // exactly ONE side stream + TWO events (R9/R12-proven safe envelope)
    cudaStream_t s2;
    cudaStreamCreateWithFlags(&s2, cudaStreamNonBlocking);
    cudaEvent_t eFork, eJoin;
    cudaEventCreateWithFlags(&eFork, cudaEventDisableTiming);
    cudaEventCreateWithFlags(&eJoin, cudaEventDisableTiming);

    // fork: W2 conversion runs concurrently with token->scan->GEMM1 chain
    cudaEventRecord(eFork, 0);
    cudaStreamWaitEvent(s2, eFork, 0);
    w2conv_kernel<<<W2C_GRID, W2C_THREADS, 0, s2>>>(W2);

    // critical prefix on stream 0
    token_w1_kernel<<<NTOK + W1_BLK, PRE_THREADS>>>(ids, emb, Wax, bax, gax, betax,
                                                    Wc, bc, gc, betac, W1);
    scan_tail_kernel<<<dim3(NCH, B_), 576>>>(decayp, mixp);
    scan_emit_kernel<<<dim3(NCH, B_), 576>>>(decayp, mixp, final_out);

    // GEMM1: h = gelu(states @ W1^T + b1)  [4096 x 512], K=576 -> fp16
    {
        dim3 g(H_ / 128, NTOK / 128);   // (4, 32)
        gemm_mma<true><<<g, 128, GEMM_SMEM_BYTES>>>(sH, w1H, b1, nullptr, hH, H_, K1_);
    }

    // join: GEMM2 needs both h (stream 0) and w2H (s2)
    cudaEventRecord(eJoin, s2);
    cudaStreamWaitEvent(0, eJoin, 0);

    // GEMM2: logits = h @ W2^T + b2  [4096 x 32000], K=512 -> fp32
    {
        dim3 g(V_ / 128, NTOK / 128);   // (250, 32)
        gemm_mma<false><<<g, 128, GEMM_SMEM_BYTES>>>(hH, w2H, b2, logits, nullptr, V_, H_);
    }
}

// round 16
// speedup vs baseline: 1.0112x; 1.0112x over previous
#include <cuda_runtime.h>
#include <cuda_fp16.h>
#include <math.h>
#include <stdint.h>

#define B_ 4
#define T_ 1024
#define E_ 256
#define V_ 32000
#define NTOK (B_*T_)
#define K1_ 576
#define H_  512
#define SCH 64                 // scan chunk length
#define NCH (T_/SCH)           // 16 chunks

// ------------------------- device scratch (static; no allocs) --------------
__device__ float  g_c[NTOK * 24];
__device__ float  g_tail[B_ * NCH * K1_];    // per-chunk tail partials
__device__ __half g_sH[NTOK * K1_];          // fp16 states
__device__ __half g_w1H[H_ * K1_];
__device__ __half g_hH[NTOK * H_];           // fp16 gelu hidden
__device__ __half g_w2H[(size_t)V_ * H_];

__device__ __forceinline__ float warp_sum(float v) {
#pragma unroll
    for (int o = 16; o > 0; o >>= 1) v += __shfl_xor_sync(0xffffffffu, v, o);
    return v;
}
__device__ __forceinline__ uint32_t smem_u32(const void* p) {
    uint32_t a;
    asm("{ .reg .u64 t; cvta.to.shared.u64 t, %1; cvt.u32.u64 %0, t; }" : "=r"(a) : "l"(p));
    return a;
}

// ---------------------------------------------------------------------------
// Kernel A: token features + W1 convert (critical path for scan/GEMM1)
// ---------------------------------------------------------------------------
#define PRE_THREADS 384
#define W1_F4 ((H_ * K1_) / 4)
#define W1_BLK ((W1_F4 + PRE_THREADS - 1) / PRE_THREADS)

__global__ void __launch_bounds__(PRE_THREADS)
token_w1_kernel(const int* __restrict__ ids, const float* __restrict__ emb,
                const float* __restrict__ Wax, const float* __restrict__ bax,
                const float* __restrict__ gax, const float* __restrict__ betax,
                const float* __restrict__ Wc,  const float* __restrict__ bc,
                const float* __restrict__ gc,  const float* __restrict__ betac,
                const float* __restrict__ W1)
{
    const int bid = blockIdx.x;
    const int tid = threadIdx.x;

    if (bid >= NTOK) {
        int idx = (bid - NTOK) * PRE_THREADS + tid;
        if (idx < W1_F4) {
            float4 v = ((const float4*)W1)[idx];
            __half2 a = __floats2half2_rn(v.x, v.y);
            __half2 b = __floats2half2_rn(v.z, v.w);
            ((__half2*)g_w1H)[idx * 2 + 0] = a;
            ((__half2*)g_w1H)[idx * 2 + 1] = b;
        }
        return;
    }

    __shared__ float xsh[E_];
    __shared__ float ash[12];
    const int n = bid;
    const int id = ids[n];
    for (int e = tid; e < E_; e += PRE_THREADS) xsh[e] = emb[(size_t)id * E_ + e];
    __syncthreads();
    const int w = tid >> 5, lane = tid & 31;
    {
        const float* wr = Wax + w * E_;
        float p = 0.f;
#pragma unroll
        for (int e = lane; e < E_; e += 32) p += xsh[e] * wr[e];
        p = warp_sum(p);
        if (lane == 0) ash[w] = p + bax[w];
    }
    __syncthreads();
    if (w == 0) {
        float v = (lane < 12) ? ash[lane] : 0.f;
        float mu = warp_sum(v) * (1.f / 12.f);
        float dv = (lane < 12) ? (v - mu) : 0.f;
        float var = warp_sum(dv * dv) * (1.f / 12.f);
        float r = rsqrtf(var + 1e-5f);
        if (lane < 12) ash[lane] = tanhf(dv * r * gax[lane] + betax[lane]);
        __syncwarp();
        float cr = 0.f;
        if (lane < 24) {
            cr = bc[lane];
#pragma unroll
            for (int k = 0; k < 12; k++) cr += ash[k] * Wc[lane * 12 + k];
        }
        float v2 = (lane < 24) ? cr : 0.f;
        float mu2 = warp_sum(v2) * (1.f / 24.f);
        float dv2 = (lane < 24) ? (cr - mu2) : 0.f;
        float var2 = warp_sum(dv2 * dv2) * (1.f / 24.f);
        float r2 = rsqrtf(var2 + 1e-5f);
        if (lane < 24) g_c[n * 24 + lane] = tanhf(dv2 * r2 * gc[lane] + betac[lane]);
    }
}

// ---------------------------------------------------------------------------
// Kernel W (side stream): W2 fp32->fp16
// ---------------------------------------------------------------------------
#define W2_F4 ((int)(((size_t)V_ * H_) / 4))
#define W2C_THREADS 256
#define W2C_HALF (W2_F4 / 2)
#define W2C_GRID (W2C_HALF / W2C_THREADS)

__global__ void __launch_bounds__(W2C_THREADS)
w2conv_kernel(const float* __restrict__ W2)
{
    int idx = blockIdx.x * W2C_THREADS + threadIdx.x;
#pragma unroll
    for (int h = 0; h < 2; h++) {
        int i = idx + h * W2C_HALF;
        float4 v = ((const float4*)W2)[i];
        __half2 a = __floats2half2_rn(v.x, v.y);
        __half2 b = __floats2half2_rn(v.z, v.w);
        ((__half2*)g_w2H)[i * 2 + 0] = a;
        ((__half2*)g_w2H)[i * 2 + 1] = b;
    }
}

// ---------------------------------------------------------------------------
// Parallel scan (R14/R15 form, frozen).
// ---------------------------------------------------------------------------
__global__ void __launch_bounds__(576)
scan_tail_kernel(const float* __restrict__ decay_p, const float* __restrict__ mix_p)
{
    __shared__ float csh[SCH * 24];
    const int k = blockIdx.x, b = blockIdx.y, tid = threadIdx.x;
    const int i = tid / 24, j = tid % 24;
    const int t0 = k * SCH;
    const float d = 1.f / (1.f + expf(-decay_p[0]));
    const float m = 1.f / (1.f + expf(-mix_p[0]));

    for (int idx = tid; idx < SCH * 24; idx += 576)
        csh[idx] = g_c[(b * T_ + t0) * 24 + idx];
    __syncthreads();

    float p = 0.f;
#pragma unroll 8
    for (int tt = 0; tt < SCH; tt++)
        p = d * p + m * csh[tt * 24 + i] * csh[tt * 24 + j];
    g_tail[(b * NCH + k) * K1_ + tid] = p;
}

__global__ void __launch_bounds__(576)
scan_emit_kernel(const float* __restrict__ decay_p, const float* __restrict__ mix_p,
                 float* __restrict__ final_out)
{
    __shared__ float csh[SCH * 24];
    const int k = blockIdx.x, b = blockIdx.y, tid = threadIdx.x;
    const int i = tid / 24, j = tid % 24;
    const int t0 = k * SCH;
    const float d = 1.f / (1.f + expf(-decay_p[0]));
    const float m = 1.f / (1.f + expf(-mix_p[0]));

    float P[NCH - 1];
#pragma unroll
    for (int jj = 0; jj < NCH - 1; jj++)
        P[jj] = (jj < k) ? g_tail[(b * NCH + jj) * K1_ + tid] : 0.f;

    for (int idx = tid; idx < SCH * 24; idx += 576)
        csh[idx] = g_c[(b * T_ + t0) * 24 + idx];

    float d64 = 1.f;
#pragma unroll
    for (int q = 0; q < SCH; q++) d64 *= d;

    float C = 0.f;
#pragma unroll
    for (int jj = 0; jj < NCH - 1; jj++)
        if (jj < k) C = d64 * C + P[jj];

    __syncthreads();

    float s = C;
#pragma unroll 8
    for (int tt = 0; tt < SCH; tt++) {
        s = d * s + m * csh[tt * 24 + i] * csh[tt * 24 + j];
        g_sH[(size_t)(b * T_ + t0 + tt) * K1_ + tid] = __float2half_rn(s);
    }
    if (k == NCH - 1) final_out[b * K1_ + tid] = s;
}

// ---------------------------------------------------------------------------
// mma.sync fp16 GEMM-NT, templated on BN (output-column tile).
// BM=128 fixed, BK=32, 128 threads = 4 warps (2m x 2n).
// BN=128: warp tile 64x64 (R8/R12 proven config, used by GEMM2).
// BN=64:  warp tile 64x32, 2x the blocks -> fills the chip for small-N GEMM1.
// 3-stage cp.async pipeline, 2 CTAs/SM.
// ---------------------------------------------------------------------------
#define PAD_K 40

template <bool GELU, int BN>
__global__ void __launch_bounds__(128, 2)
gemm_mma(const __half* __restrict__ A, const __half* __restrict__ Bm,
         const float* __restrict__ bias, float* __restrict__ outF,
         __half* __restrict__ outH, int N, int K)
{
    constexpr int A_TILE = 128 * PAD_K;          // halves
    constexpr int B_TILE = BN * PAD_K;           // halves
    constexpr int STAGE  = A_TILE + B_TILE;      // halves per stage
    constexpr int NSTAGE = 3;
    constexpr int NT = BN / 16;                  // n-tiles per warp (8 or 4)

    extern __shared__ __half sm[];
    const int tid  = threadIdx.x;
    const int wid  = tid >> 5, lane = tid & 31;
    const int wm   = wid >> 1;          // 0..1 (64-row slab)
    const int wn   = wid & 1;           // 0..1 (BN/2-col slab)
    const int r0   = blockIdx.y * 128;
    const int c0   = blockIdx.x * BN;

    const uint32_t smb = smem_u32(sm);

    float acc[4][NT][4];
#pragma unroll
    for (int i = 0; i < 4; i++)
#pragma unroll
        for (int j = 0; j < NT; j++)
#pragma unroll
            for (int q = 0; q < 4; q++) acc[i][j][q] = 0.f;

    const int NS = K / 32;

    auto load_stage = [&](int ci, int st) {
        const int k0 = ci * 32;
        const uint32_t aBase = smb + (uint32_t)(st * STAGE) * 2;
        const uint32_t bBase = aBase + (uint32_t)A_TILE * 2;
#pragma unroll
        for (int p = 0; p < 4; p++) {               // A: 128 rows x 4 chunks
            int idx = tid + p * 128;
            int row = idx >> 2;
            int c4  = idx & 3;
            const __half* gs = A + (size_t)(r0 + row) * K + k0 + c4 * 8;
            uint32_t sd = aBase + (uint32_t)(row * PAD_K + c4 * 8) * 2;
            asm volatile("cp.async.cg.shared.global [%0], [%1], 16;" :: "r"(sd), "l"(gs));
        }
#pragma unroll
        for (int p = 0; p < BN / 32; p++) {         // B: BN rows x 4 chunks
            int idx = tid + p * 128;
            int row = idx >> 2;
            int c4  = idx & 3;
            const __half* gs = Bm + (size_t)(c0 + row) * K + k0 + c4 * 8;
            uint32_t sd = bBase + (uint32_t)(row * PAD_K + c4 * 8) * 2;
            asm volatile("cp.async.cg.shared.global [%0], [%1], 16;" :: "r"(sd), "l"(gs));
        }
        asm volatile("cp.async.commit_group;" ::: "memory");
    };

    load_stage(0, 0);
    load_stage(1, 1);

    for (int ci = 0; ci < NS; ci++) {
        const int st = ci % NSTAGE;
        if (ci == NS - 1) asm volatile("cp.async.wait_group 0;" ::: "memory");
        else              asm volatile("cp.async.wait_group 1;" ::: "memory");
        __syncthreads();
        if (ci + 2 < NS) load_stage(ci + 2, (ci + 2) % NSTAGE);

        const uint32_t aBase = smb + (uint32_t)(st * STAGE) * 2;
        const uint32_t bBase = aBase + (uint32_t)A_TILE * 2;

#pragma unroll
        for (int kk = 0; kk < 2; kk++) {
            const int kb = kk * 16;
            uint32_t afr[4][4];
            uint32_t bfr[NT][2];
#pragma unroll
            for (int mt = 0; mt < 4; mt++) {
                uint32_t addr = aBase +
                    (uint32_t)((wm * 64 + mt * 16 + (lane & 15)) * PAD_K + kb + (lane >> 4) * 8) * 2;
                asm volatile("ldmatrix.sync.aligned.m8n8.x4.shared.b16 {%0,%1,%2,%3}, [%4];"
                             : "=r"(afr[mt][0]), "=r"(afr[mt][1]), "=r"(afr[mt][2]), "=r"(afr[mt][3])
                             : "r"(addr));
            }
#pragma unroll
            for (int ntp = 0; ntp < NT / 2; ntp++) {
                uint32_t row = wn * (BN / 2) + ntp * 16 + ((lane >> 4) & 1) * 8 + (lane & 7);
                uint32_t kof = kb + ((lane >> 3) & 1) * 8;
                uint32_t addr = bBase + (uint32_t)(row * PAD_K + kof) * 2;
                asm volatile("ldmatrix.sync.aligned.m8n8.x4.shared.b16 {%0,%1,%2,%3}, [%4];"
                             : "=r"(bfr[ntp * 2][0]),     "=r"(bfr[ntp * 2][1]),
                               "=r"(bfr[ntp * 2 + 1][0]), "=r"(bfr[ntp * 2 + 1][1])
                             : "r"(addr));
            }
#pragma unroll
            for (int mt = 0; mt < 4; mt++)
#pragma unroll
                for (int nt = 0; nt < NT; nt++) {
                    asm volatile(
                        "mma.sync.aligned.m16n8k16.row.col.f32.f16.f16.f32 "
                        "{%0,%1,%2,%3}, {%4,%5,%6,%7}, {%8,%9}, {%0,%1,%2,%3};"
                        : "+f"(acc[mt][nt][0]), "+f"(acc[mt][nt][1]),
                          "+f"(acc[mt][nt][2]), "+f"(acc[mt][nt][3])
                        : "r"(afr[mt][0]), "r"(afr[mt][1]), "r"(afr[mt][2]), "r"(afr[mt][3]),
                          "r"(bfr[nt][0]), "r"(bfr[nt][1]));
                }
        }
    }

    const int g  = lane >> 2;
    const int tg = lane & 3;
#pragma unroll
    for (int nt = 0; nt < NT; nt++) {
        const int col = c0 + wn * (BN / 2) + nt * 8 + tg * 2;
        const float bi0 = __ldg(bias + col);
        const float bi1 = __ldg(bias + col + 1);
#pragma unroll
        for (int mt = 0; mt < 4; mt++) {
            const int row = r0 + wm * 64 + mt * 16 + g;
            float x0 = acc[mt][nt][0] + bi0;
            float x1 = acc[mt][nt][1] + bi1;
            float x2 = acc[mt][nt][2] + bi0;
            float x3 = acc[mt][nt][3] + bi1;
            if (GELU) {
                x0 = 0.5f * x0 * (1.f + erff(x0 * 0.70710678118654752f));
                x1 = 0.5f * x1 * (1.f + erff(x1 * 0.70710678118654752f));
                x2 = 0.5f * x2 * (1.f + erff(x2 * 0.70710678118654752f));
                x3 = 0.5f * x3 * (1.f + erff(x3 * 0.70710678118654752f));
                *(__half2*)(outH + (size_t)row * N + col)       = __floats2half2_rn(x0, x1);
                *(__half2*)(outH + (size_t)(row + 8) * N + col) = __floats2half2_rn(x2, x3);
            } else {
                *(float2*)(outF + (size_t)row * N + col)       = make_float2(x0, x1);
                *(float2*)(outF + (size_t)(row + 8) * N + col) = make_float2(x2, x3);
            }
        }
    }
}

#define SMEM_BN128 (3 * (128 + 128) * PAD_K * 2)   // 61440 B
#define SMEM_BN64  (3 * (128 + 64)  * PAD_K * 2)   // 46080 B

// ---------------------------------------------------------------------------
extern "C" void kernel_launch(void* const* d_in, const int* in_sizes, int n_in,
                              void* d_out, int out_size)
{
    const int*   ids    = (const int*)  d_in[0];
    const float* emb    = (const float*)d_in[1];
    const float* Wax    = (const float*)d_in[2];
    const float* bax    = (const float*)d_in[3];
    const float* gax    = (const float*)d_in[4];
    const float* betax  = (const float*)d_in[5];
    const float* Wc     = (const float*)d_in[6];
    const float* bc     = (const float*)d_in[7];
    const float* gc     = (const float*)d_in[8];
    const float* betac  = (const float*)d_in[9];
    const float* decayp = (const float*)d_in[10];
    const float* mixp   = (const float*)d_in[11];
    const float* W1     = (const float*)d_in[12];
    const float* b1     = (const float*)d_in[13];
    const float* W2     = (const float*)d_in[14];
    const float* b2     = (const float*)d_in[15];

    float* out       = (float*)d_out;
    float* logits    = out;
    float* final_out = out + (size_t)NTOK * V_;

    __half *sH, *w1H, *hH, *w2H;
    cudaGetSymbolAddress((void**)&sH,  g_sH);
    cudaGetSymbolAddress((void**)&w1H, g_w1H);
    cudaGetSymbolAddress((void**)&hH,  g_hH);
    cudaGetSymbolAddress((void**)&w2H, g_w2H);

    cudaFuncSetAttribute((const void*)gemm_mma<true, 64>,
                         cudaFuncAttributeMaxDynamicSharedMemorySize, SMEM_BN64);
    cudaFuncSetAttribute((const void*)gemm_mma<false, 128>,
                         cudaFuncAttributeMaxDynamicSharedMemorySize, SMEM_BN128);

    // exactly ONE side stream + TWO events (R9/R12-proven safe envelope)
    cudaStream_t s2;
    cudaStreamCreateWithFlags(&s2, cudaStreamNonBlocking);
    cudaEvent_t eFork, eJoin;
    cudaEventCreateWithFlags(&eFork, cudaEventDisableTiming);
    cudaEventCreateWithFlags(&eJoin, cudaEventDisableTiming);

    // fork: W2 conversion runs concurrently with token->scan->GEMM1 chain
    cudaEventRecord(eFork, 0);
    cudaStreamWaitEvent(s2, eFork, 0);
    w2conv_kernel<<<W2C_GRID, W2C_THREADS, 0, s2>>>(W2);

    // critical prefix on stream 0
    token_w1_kernel<<<NTOK + W1_BLK, PRE_THREADS>>>(ids, emb, Wax, bax, gax, betax,
                                                    Wc, bc, gc, betac, W1);
    scan_tail_kernel<<<dim3(NCH, B_), 576>>>(decayp, mixp);
    scan_emit_kernel<<<dim3(NCH, B_), 576>>>(decayp, mixp, final_out);

    // GEMM1: h = gelu(states @ W1^T + b1)  [4096 x 512], K=576 -> fp16
    // BN=64 -> (8, 32) = 256 blocks: fills the chip (was 128 blocks)
    {
        dim3 g(H_ / 64, NTOK / 128);
        gemm_mma<true, 64><<<g, 128, SMEM_BN64>>>(sH, w1H, b1, nullptr, hH, H_, K1_);
    }

    // join: GEMM2 needs both h (stream 0) and w2H (s2)
    cudaEventRecord(eJoin, s2);
    cudaStreamWaitEvent(0, eJoin, 0);

    // GEMM2: logits = h @ W2^T + b2  [4096 x 32000], K=512 -> fp32
    {
        dim3 g(V_ / 128, NTOK / 128);   // (250, 32)
        gemm_mma<false, 128><<<g, 128, SMEM_BN128>>>(hH, w2H, b2, logits, nullptr, V_, H_);
    }
}